// round 1
// baseline (speedup 1.0000x reference)
#include <cuda_runtime.h>
#include <float.h>

#define NCODES   4096
#define CDIM     64
#define NTOK     65536
#define HW       4096
#define TOK_BLK  128
#define CODE_CHUNK 128
#define THREADS  256

// smem layout (floats):
//   zs   : CDIM * TOK_BLK          = 8192
//   es   : CODE_CHUNK * 65         = 8320   (pad 65 -> conflict-free scalar reads)
//   esq  : CODE_CHUNK              = 128
//   sidx : TOK_BLK (as int)        = 128
#define SMEM_FLOATS (CDIM*TOK_BLK + CODE_CHUNK*65 + CODE_CHUNK + TOK_BLK)
#define SMEM_BYTES  (SMEM_FLOATS * 4)

__device__ float g_esq[NCODES];

// ||e||^2 per code: one warp per code.
__global__ void esq_kernel(const float* __restrict__ emb) {
    int warp = (blockIdx.x * blockDim.x + threadIdx.x) >> 5;
    int lane = threadIdx.x & 31;
    if (warp >= NCODES) return;
    const float* row = emb + (size_t)warp * CDIM;
    float v0 = row[lane];
    float v1 = row[lane + 32];
    float s = v0 * v0 + v1 * v1;
    #pragma unroll
    for (int off = 16; off; off >>= 1)
        s += __shfl_xor_sync(0xffffffffu, s, off);
    if (lane == 0) g_esq[warp] = s;
}

__global__ __launch_bounds__(THREADS, 2)
void vq_kernel(const float* __restrict__ z,
               const float* __restrict__ emb,
               float* __restrict__ out) {
    extern __shared__ float sm[];
    float* zs    = sm;                            // [CDIM][TOK_BLK]
    float* es    = zs + CDIM * TOK_BLK;           // [CODE_CHUNK][65]
    float* esq_s = es + CODE_CHUNK * 65;          // [CODE_CHUNK]
    int*   sidx  = (int*)(esq_s + CODE_CHUNK);    // [TOK_BLK]

    const int t   = threadIdx.x;
    const int n0  = blockIdx.x * TOK_BLK;
    const int b   = n0 >> 12;          // HW = 4096
    const int hw0 = n0 & (HW - 1);     // blocks never cross batch (4096 % 128 == 0)

    const float* zb = z + (size_t)b * CDIM * HW + hw0;

    // Load z tile. z is (B,C,H,W): for fixed c, 128 consecutive tokens are
    // contiguous in gmem -> coalesced loads, conflict-free smem writes, no transpose.
    for (int i = t; i < CDIM * TOK_BLK; i += THREADS) {
        int c   = i >> 7;        // / TOK_BLK
        int tok = i & (TOK_BLK - 1);
        zs[c * TOK_BLK + tok] = zb[(size_t)c * HW + tok];
    }

    const int ti = t >> 4;   // token group 0..15 -> tokens ti + 16k
    const int ci = t & 15;   // code  group 0..15 -> codes  ci + 16m  (half-warp reducible)

    float best[8];
    int   bidx[8];
    #pragma unroll
    for (int k = 0; k < 8; k++) { best[k] = FLT_MAX; bidx[k] = 0; }

    for (int base = 0; base < NCODES; base += CODE_CHUNK) {
        __syncthreads();   // protect es reuse from previous chunk / gather
        // Load code chunk: es[code][c], row pad 65.
        for (int i = t; i < CODE_CHUNK * CDIM; i += THREADS) {
            int code = i >> 6;
            int c    = i & 63;
            es[code * 65 + c] = emb[(size_t)(base + code) * CDIM + c];
        }
        if (t < CODE_CHUNK) esq_s[t] = g_esq[base + t];
        __syncthreads();

        float acc[8][8];
        #pragma unroll
        for (int k = 0; k < 8; k++)
            #pragma unroll
            for (int m = 0; m < 8; m++)
                acc[k][m] = 0.0f;

        #pragma unroll 4
        for (int c = 0; c < CDIM; c++) {
            float a[8], bb[8];
            #pragma unroll
            for (int k = 0; k < 8; k++)
                a[k] = zs[c * TOK_BLK + ti + 16 * k];       // broadcast, conflict-free
            #pragma unroll
            for (int m = 0; m < 8; m++)
                bb[m] = es[(ci + 16 * m) * 65 + c];          // pad-65 -> conflict-free
            #pragma unroll
            for (int k = 0; k < 8; k++)
                #pragma unroll
                for (int m = 0; m < 8; m++)
                    acc[k][m] = fmaf(a[k], bb[m], acc[k][m]);
        }

        // Per-thread argmin update (codes ascending in m -> first-min tiebreak kept).
        #pragma unroll
        for (int k = 0; k < 8; k++) {
            #pragma unroll
            for (int m = 0; m < 8; m++) {
                float s = esq_s[ci + 16 * m] - 2.0f * acc[k][m];
                int code = base + ci + 16 * m;
                if (s < best[k]) { best[k] = s; bidx[k] = code; }
            }
        }
    }

    // Reduce argmin over the 16 code-group threads (contiguous half-warp).
    #pragma unroll
    for (int k = 0; k < 8; k++) {
        float v  = best[k];
        int   id = bidx[k];
        #pragma unroll
        for (int off = 8; off; off >>= 1) {
            float ov  = __shfl_xor_sync(0xffffffffu, v,  off, 16);
            int   oid = __shfl_xor_sync(0xffffffffu, id, off, 16);
            if (ov < v || (ov == v && oid < id)) { v = ov; id = oid; }
        }
        if (ci == 0) sidx[ti + 16 * k] = id;
    }
    __syncthreads();

    // Gather emb[idx] and write transposed to (B,C,H,W) via smem stage (reuse es).
    float* st = es;   // [TOK_BLK][65]
    for (int i = t; i < TOK_BLK * CDIM; i += THREADS) {
        int tok = i >> 6;
        int c   = i & 63;
        st[tok * 65 + c] = emb[(size_t)sidx[tok] * CDIM + c];   // coalesced row reads
    }
    __syncthreads();
    float* ob = out + (size_t)b * CDIM * HW + hw0;
    for (int i = t; i < CDIM * TOK_BLK; i += THREADS) {
        int c   = i >> 7;
        int tok = i & (TOK_BLK - 1);
        ob[(size_t)c * HW + tok] = st[tok * 65 + c];            // coalesced writes
    }
}

extern "C" void kernel_launch(void* const* d_in, const int* in_sizes, int n_in,
                              void* d_out, int out_size) {
    const float* z   = (const float*)d_in[0];
    const float* emb = (const float*)d_in[1];
    float* out = (float*)d_out;

    cudaFuncSetAttribute(vq_kernel, cudaFuncAttributeMaxDynamicSharedMemorySize, SMEM_BYTES);

    esq_kernel<<<NCODES / 8, 256>>>(emb);
    vq_kernel<<<NTOK / TOK_BLK, THREADS, SMEM_BYTES>>>(z, emb, out);
}

// round 3
// speedup vs baseline: 2.2951x; 2.2951x over previous
#include <cuda_runtime.h>
#include <cuda_fp16.h>
#include <float.h>
#include <stdint.h>

#define NCODES   4096
#define CDIM     64
#define NTOK     65536
#define HW       4096
#define M_TILE   128
#define N_CHUNK  128
#define NCHUNKS  32
#define THREADS  256
#define SCALE    64.0f
#define ESQ_SCALE 4096.0f   // SCALE^2

// ---- smem byte offsets ----
// zs:   64 x 132 fp32 (padded)        = 33792
// esq:  4096 fp32 (pre-scaled)        = 16384
// B tiles: [128][72] halves, hi/lo, double buffered = 4 x 18432
// cand/sidx small tail
#define OFF_ZS     0
#define OFF_ESQ    33792
#define OFF_BH0    50176
#define OFF_BL0    68608
#define OFF_BH1    87040
#define OFF_BL1    105472
#define OFF_CANDV  123904
#define OFF_CANDI  124928
#define OFF_SIDX   125952
#define SMEM_TOTAL 126464

#define B_STRIDE_B 144   // 72 halves per row -> conflict-free ldmatrix/LDS

__device__ float g_esq[NCODES];

__device__ __forceinline__ uint32_t smem_u32(const void* p) {
    uint32_t a;
    asm("{ .reg .u64 t; cvta.to.shared.u64 t, %1; cvt.u32.u64 %0, t; }" : "=r"(a) : "l"(p));
    return a;
}

__device__ __forceinline__ void split2(float v0, float v1, uint32_t& hi, uint32_t& lo) {
    __half h0 = __float2half_rn(v0);
    __half h1 = __float2half_rn(v1);
    __half l0 = __float2half_rn(v0 - __half2float(h0));
    __half l1 = __float2half_rn(v1 - __half2float(h1));
    hi = (uint32_t)__half_as_ushort(h0) | ((uint32_t)__half_as_ushort(h1) << 16);
    lo = (uint32_t)__half_as_ushort(l0) | ((uint32_t)__half_as_ushort(l1) << 16);
}

__device__ __forceinline__ void mma16816(float* c, const uint32_t* a, uint32_t b0, uint32_t b1) {
    asm volatile(
        "mma.sync.aligned.m16n8k16.row.col.f32.f16.f16.f32 "
        "{%0,%1,%2,%3}, {%4,%5,%6,%7}, {%8,%9}, {%0,%1,%2,%3};"
        : "+f"(c[0]), "+f"(c[1]), "+f"(c[2]), "+f"(c[3])
        : "r"(a[0]), "r"(a[1]), "r"(a[2]), "r"(a[3]), "r"(b0), "r"(b1));
}

__device__ __forceinline__ void ldmx4(uint32_t& r0, uint32_t& r1, uint32_t& r2, uint32_t& r3,
                                      uint32_t a) {
    asm volatile("ldmatrix.sync.aligned.m8n8.x4.shared.b16 {%0,%1,%2,%3}, [%4];"
        : "=r"(r0), "=r"(r1), "=r"(r2), "=r"(r3) : "r"(a));
}

// ||e||^2 per code (one warp per code)
__global__ void esq_kernel(const float* __restrict__ emb) {
    int warp = (blockIdx.x * blockDim.x + threadIdx.x) >> 5;
    int lane = threadIdx.x & 31;
    if (warp >= NCODES) return;
    const float* row = emb + (size_t)warp * CDIM;
    float v0 = row[lane], v1 = row[lane + 32];
    float s = v0 * v0 + v1 * v1;
    #pragma unroll
    for (int off = 16; off; off >>= 1) s += __shfl_xor_sync(0xffffffffu, s, off);
    if (lane == 0) g_esq[warp] = s;
}

__global__ __launch_bounds__(THREADS, 1)
void vq_kernel(const float* __restrict__ z,
               const float* __restrict__ emb,
               float* __restrict__ out) {
    extern __shared__ char sm[];
    float* zs    = (float*)(sm + OFF_ZS);
    float* esq_s = (float*)(sm + OFF_ESQ);
    float* candv = (float*)(sm + OFF_CANDV);
    int*   candi = (int*)(sm + OFF_CANDI);
    int*   sidx  = (int*)(sm + OFF_SIDX);

    const int tid  = threadIdx.x;
    const int lane = tid & 31;
    const int wid  = tid >> 5;
    const int grp  = lane >> 2;     // 0..7
    const int tid4 = lane & 3;      // 0..3
    const int mwarp = wid >> 1;     // 0..3 : token rows mwarp*32..+31
    const int nw    = wid & 1;      // 0..1 : code cols nw*64..+63

    const int n0  = blockIdx.x * M_TILE;
    const int b   = n0 >> 12;
    const int hw0 = n0 & (HW - 1);
    const float* zb = z + (size_t)b * CDIM * HW + hw0;

    // ---- prefetch chunk 0 of emb ----
    const float4* e4 = (const float4*)emb;
    const int prow = tid >> 4;      // 0..15 (then +16*j)
    const int pq   = tid & 15;      // float4 index within row (k = pq*4..+3)
    float4 pref[8];
    #pragma unroll
    for (int j = 0; j < 8; j++)
        pref[j] = e4[(size_t)(prow + j * 16) * 16 + pq];

    // ---- stage z tile (scaled) ----
    for (int i = tid; i < CDIM * M_TILE; i += THREADS) {
        int c = i >> 7, tok = i & (M_TILE - 1);
        zs[c * 132 + tok] = zb[(size_t)c * HW + tok] * SCALE;
    }
    // ---- esq (pre-scaled) ----
    #pragma unroll
    for (int j = 0; j < 16; j++)
        esq_s[tid + j * 256] = g_esq[tid + j * 256] * ESQ_SCALE;
    __syncthreads();

    // ---- build A fragments in registers (hi/lo) ----
    uint32_t Ah[2][4][4], Al[2][4][4];
    #pragma unroll
    for (int m = 0; m < 2; m++) {
        int r0 = mwarp * 32 + m * 16 + grp;
        #pragma unroll
        for (int s = 0; s < 4; s++) {
            int kb = 2 * tid4 + 16 * s;
            split2(zs[kb * 132 + r0],           zs[(kb + 1) * 132 + r0],     Ah[m][s][0], Al[m][s][0]);
            split2(zs[kb * 132 + r0 + 8],       zs[(kb + 1) * 132 + r0 + 8], Ah[m][s][1], Al[m][s][1]);
            split2(zs[(kb + 8) * 132 + r0],     zs[(kb + 9) * 132 + r0],     Ah[m][s][2], Al[m][s][2]);
            split2(zs[(kb + 8) * 132 + r0 + 8], zs[(kb + 9) * 132 + r0 + 8], Ah[m][s][3], Al[m][s][3]);
        }
    }

    // ---- convert + store chunk 0 into buffer 0 ----
    const uint32_t bh_base[2] = { smem_u32(sm + OFF_BH0), smem_u32(sm + OFF_BH1) };
    const uint32_t bl_base[2] = { smem_u32(sm + OFF_BL0), smem_u32(sm + OFF_BL1) };
    {
        char* bh = sm + OFF_BH0;
        char* bl = sm + OFF_BL0;
        #pragma unroll
        for (int j = 0; j < 8; j++) {
            int row = prow + j * 16;
            float4 v = pref[j];
            uint32_t h0, l0, h1, l1;
            split2(v.x * SCALE, v.y * SCALE, h0, l0);
            split2(v.z * SCALE, v.w * SCALE, h1, l1);
            *(uint2*)(bh + row * B_STRIDE_B + pq * 8) = make_uint2(h0, h1);
            *(uint2*)(bl + row * B_STRIDE_B + pq * 8) = make_uint2(l0, l1);
        }
    }
    __syncthreads();

    // ldmatrix lane address pieces: matrices (f0,klo),(f0,khi),(f1,klo),(f1,khi)
    const int lrow  = (lane & 7) + ((lane >> 4) & 1) * 8;   // row within 16-row f-pair block
    const int lkoff = ((lane >> 3) & 1) * 16;               // khalf byte offset
    const uint32_t baddr = (uint32_t)(nw * 64 + lrow) * B_STRIDE_B + lkoff;

    float best[4];
    int   bidx[4];
    #pragma unroll
    for (int g = 0; g < 4; g++) { best[g] = FLT_MAX; bidx[g] = 0; }

    for (int ch = 0; ch < NCHUNKS; ch++) {
        const int buf = ch & 1;

        if (ch < NCHUNKS - 1) {
            size_t gbase = (size_t)((ch + 1) * N_CHUNK + prow) * 16 + pq;
            #pragma unroll
            for (int j = 0; j < 8; j++)
                pref[j] = e4[gbase + j * 256];
        }

        float acc[2][8][4];
        #pragma unroll
        for (int m = 0; m < 2; m++)
            #pragma unroll
            for (int f = 0; f < 8; f++)
                #pragma unroll
                for (int r = 0; r < 4; r++)
                    acc[m][f][r] = 0.0f;

        const uint32_t bhb = bh_base[buf] + baddr;
        const uint32_t blb = bl_base[buf] + baddr;
        #pragma unroll
        for (int s = 0; s < 4; s++) {
            #pragma unroll
            for (int fp = 0; fp < 4; fp++) {
                uint32_t h0, h1, h2, h3, L0, L1, L2, L3;
                ldmx4(h0, h1, h2, h3, bhb + fp * (16 * B_STRIDE_B) + s * 32);
                ldmx4(L0, L1, L2, L3, blb + fp * (16 * B_STRIDE_B) + s * 32);
                const int f0 = fp * 2, f1 = fp * 2 + 1;
                mma16816(acc[0][f0], Ah[0][s], h0, h1);
                mma16816(acc[1][f0], Ah[1][s], h0, h1);
                mma16816(acc[0][f1], Ah[0][s], h2, h3);
                mma16816(acc[1][f1], Ah[1][s], h2, h3);
                mma16816(acc[0][f0], Ah[0][s], L0, L1);
                mma16816(acc[1][f0], Ah[1][s], L0, L1);
                mma16816(acc[0][f1], Ah[0][s], L2, L3);
                mma16816(acc[1][f1], Ah[1][s], L2, L3);
                mma16816(acc[0][f0], Al[0][s], h0, h1);
                mma16816(acc[1][f0], Al[1][s], h0, h1);
                mma16816(acc[0][f1], Al[0][s], h2, h3);
                mma16816(acc[1][f1], Al[1][s], h2, h3);
            }
        }

        // ---- fused argmin epilogue ----
        const int cb = ch * N_CHUNK + nw * 64;
        float2 ee[8];
        #pragma unroll
        for (int f = 0; f < 8; f++)
            ee[f] = *(const float2*)&esq_s[cb + f * 8 + 2 * tid4];

        #pragma unroll
        for (int m = 0; m < 2; m++) {
            #pragma unroll
            for (int h = 0; h < 2; h++) {
                const int g = m * 2 + h;
                float sv[16];
                #pragma unroll
                for (int f = 0; f < 8; f++) {
                    sv[2 * f]     = fmaf(acc[m][f][h * 2 + 0], -2.0f, ee[f].x);
                    sv[2 * f + 1] = fmaf(acc[m][f][h * 2 + 1], -2.0f, ee[f].y);
                }
                float mn = sv[0];
                #pragma unroll
                for (int j = 1; j < 16; j++) mn = fminf(mn, sv[j]);
                if (mn < best[g]) {
                    best[g] = mn;
                    int found = -1;
                    #pragma unroll
                    for (int j = 0; j < 16; j++)
                        if (found < 0 && sv[j] == mn)
                            found = cb + (j >> 1) * 8 + 2 * tid4 + (j & 1);
                    bidx[g] = found;
                }
            }
        }

        if (ch < NCHUNKS - 1) {
            char* bh = sm + (buf ? OFF_BH0 : OFF_BH1);
            char* bl = sm + (buf ? OFF_BL0 : OFF_BL1);
            #pragma unroll
            for (int j = 0; j < 8; j++) {
                int row = prow + j * 16;
                float4 v = pref[j];
                uint32_t h0, l0, h1, l1;
                split2(v.x * SCALE, v.y * SCALE, h0, l0);
                split2(v.z * SCALE, v.w * SCALE, h1, l1);
                *(uint2*)(bh + row * B_STRIDE_B + pq * 8) = make_uint2(h0, h1);
                *(uint2*)(bl + row * B_STRIDE_B + pq * 8) = make_uint2(l0, l1);
            }
        }
        __syncthreads();
    }

    // ---- cross-thread argmin reduction ----
    #pragma unroll
    for (int g = 0; g < 4; g++) {
        float v = best[g];
        int   id = bidx[g];
        #pragma unroll
        for (int off = 1; off <= 2; off <<= 1) {
            float ov = __shfl_xor_sync(0xffffffffu, v, off);
            int   oi = __shfl_xor_sync(0xffffffffu, id, off);
            if (ov < v || (ov == v && oi < id)) { v = ov; id = oi; }
        }
        if (tid4 == 0) {
            int token = mwarp * 32 + (g >> 1) * 16 + grp + (g & 1) * 8;
            candv[nw * 128 + token] = v;
            candi[nw * 128 + token] = id;
        }
    }
    __syncthreads();
    if (tid < 128) {
        float v0 = candv[tid], v1 = candv[128 + tid];
        int   i0 = candi[tid], i1 = candi[128 + tid];
        sidx[tid] = (v1 < v0 || (v1 == v0 && i1 < i0)) ? i1 : i0;
    }
    __syncthreads();

    // ---- gather emb[idx], write transposed & coalesced (stage in zs region) ----
    float* st = zs;   // [128][65]
    for (int i = tid; i < M_TILE * CDIM; i += THREADS) {
        int tok = i >> 6, c = i & 63;
        st[tok * 65 + c] = emb[(size_t)sidx[tok] * CDIM + c];
    }
    __syncthreads();
    float* ob = out + (size_t)b * CDIM * HW + hw0;
    for (int i = tid; i < CDIM * M_TILE; i += THREADS) {
        int c = i >> 7, tok = i & (M_TILE - 1);
        ob[(size_t)c * HW + tok] = st[tok * 65 + c];
    }
}

extern "C" void kernel_launch(void* const* d_in, const int* in_sizes, int n_in,
                              void* d_out, int out_size) {
    const float* z   = (const float*)d_in[0];
    const float* emb = (const float*)d_in[1];
    float* out = (float*)d_out;

    cudaFuncSetAttribute(vq_kernel, cudaFuncAttributeMaxDynamicSharedMemorySize, SMEM_TOTAL);

    esq_kernel<<<NCODES / 8, 256>>>(emb);
    vq_kernel<<<NTOK / M_TILE, THREADS, SMEM_TOTAL>>>(z, emb, out);
}